// round 9
// baseline (speedup 1.0000x reference)
#include <cuda_runtime.h>
#include <cstdint>

// Spatial correlation sampler:
// out[b, di*9+dj, i, j] = (1/C) * sum_c x[b,c,i,j] * y[b,c,i+di-4, j+dj-4]  (zero-padded)
// x,y = [16, 256, 64, 64] fp32; out = [16, 81, 64, 64] fp32.

#define BB 16
#define CH 256
#define HH 64
#define WW 64
#define TH 4            // output rows per CTA
#define CC 4            // channels per smem stage (2 per thread-half)
#define NS (CH / CC)    // 64 stages
#define DI_CHUNK 3
#define YR (TH + 2)     // 6 y rows per stage
#define YW 72           // 64 + 2*4 pad
#define NBUF 3          // cp.async ring depth

#define FMA2(acc, a, b) \
    asm("fma.rn.f32x2 %0, %1, %2, %0;" : "+l"(acc) : "l"(a), "l"(b))
#define PACK2(r, lo, hi) \
    asm("mov.b64 %0, {%1, %2};" : "=l"(r) : "r"(__float_as_uint(lo)), "r"(__float_as_uint(hi)))
#define UNPK2(lo, hi, r) \
    asm("mov.b64 {%0, %1}, %2;" : "=f"(lo), "=f"(hi) : "l"(r))

__device__ __forceinline__ void cpa16(uint32_t saddr, const void* gptr, int src_bytes) {
    asm volatile("cp.async.cg.shared.global [%0], [%1], 16, %2;\n"
                 :: "r"(saddr), "l"(gptr), "r"(src_bytes));
}
__device__ __forceinline__ void cpa_commit() {
    asm volatile("cp.async.commit_group;\n");
}

// Smem: cp.async ring (union'd with the epilogue reduction buffer).
struct Bufs {
    float xs[NBUF][CC][TH][WW];   // 3*4*4*64*4  = 12288 B
    float ys[NBUF][CC][YR][YW];   // 3*4*6*72*4  = 20736 B
};
#define RED_STRIDE 109            // odd stride -> conflict-free
#define SMEM_BYTES (sizeof(Bufs) > 64 * RED_STRIDE * 4 ? sizeof(Bufs) : 64 * RED_STRIDE * 4)

__global__ __launch_bounds__(128, 2)
void corr_kernel(const float* __restrict__ x,
                 const float* __restrict__ y,
                 float* __restrict__ out)
{
    __shared__ __align__(16) unsigned char smem_raw[SMEM_BYTES];
    Bufs* S = reinterpret_cast<Bufs*>(smem_raw);
    float (*red)[RED_STRIDE] = reinterpret_cast<float (*)[RED_STRIDE]>(smem_raw);

    const int tid = threadIdx.x;          // 128
    const int jg  = tid & 15;             // 16 col groups
    const int row = (tid >> 4) & 3;       // 4 output rows
    const int h   = tid >> 6;             // channel half (0/1)
    const int j0  = jg * 4;               // 4 pixels per thread
    const int i0  = blockIdx.x * TH;      // 16 i-tiles
    const int g   = blockIdx.y * DI_CHUNK;
    const int b   = blockIdx.z;           // batch slowest -> L2 locality

    const float* xb = x + (size_t)b * CH * HH * WW;
    const float* yb = y + (size_t)b * CH * HH * WW;

    const uint32_t xs_s = (uint32_t)__cvta_generic_to_shared(&S->xs[0][0][0][0]);
    const uint32_t ys_s = (uint32_t)__cvta_generic_to_shared(&S->ys[0][0][0][0]);
    const uint32_t xs_sz = sizeof(float) * CC * TH * WW;    // per-buffer
    const uint32_t ys_sz = sizeof(float) * CC * YR * YW;

    unsigned long long acc2[DI_CHUNK][9][2];
#pragma unroll
    for (int a = 0; a < DI_CHUNK; a++)
#pragma unroll
        for (int d = 0; d < 9; d++) { acc2[a][d][0] = 0ull; acc2[a][d][1] = 0ull; }

    // ---- async stage loader: gmem -> ring buffer `sel` for channel block `st`
    auto issue_stage = [&](int st, int sel) {
        const int cc0 = st * CC;
        // x tile: 4c*4r*16q4 = 256 float4, 2 per thread
#pragma unroll
        for (int e = 0; e < 2; e++) {
            int f   = tid + e * 128;
            int c   = f >> 6;
            int rem = f & 63;
            int r   = rem >> 4;
            int q4  = rem & 15;
            const float* g4 = &xb[(size_t)(cc0 + c) * HH * WW + (i0 + r) * WW + q4 * 4];
            cpa16(xs_s + sel * xs_sz + (uint32_t)f * 16u, g4, 16);
        }
        // y tile: 4c*6r*18q = 432 float4, zero-padded edges
#pragma unroll
        for (int e = 0; e < 4; e++) {
            int f = tid + e * 128;
            if (f < CC * YR * 18) {
                int c   = f / (YR * 18);
                int rem = f % (YR * 18);
                int r   = rem / 18;
                int q   = rem % 18;
                int gy  = i0 + g - 4 + r;
                bool ok = (gy >= 0) && (gy < HH) && (q > 0) && (q < 17);
                int gyc = gy < 0 ? 0 : (gy > HH - 1 ? HH - 1 : gy);
                int gq  = ok ? (q * 4 - 4) : 0;
                const float* g4 = &yb[(size_t)(cc0 + c) * HH * WW + gyc * WW + gq];
                uint32_t saddr = ys_s + sel * ys_sz
                               + (uint32_t)(((c * YR + r) * YW) + q * 4) * 4u;
                cpa16(saddr, g4, ok ? 16 : 0);
            }
        }
        cpa_commit();
    };

    issue_stage(0, 0);
    issue_stage(1, 1);

    for (int t = 0; t < NS; t++) {
        const int sel = t % NBUF;
        if (t < NS - 1) asm volatile("cp.async.wait_group 1;\n");
        else            asm volatile("cp.async.wait_group 0;\n");
        __syncthreads();                      // single barrier per stage
        if (t + 2 < NS) issue_stage(t + 2, (t + 2) % NBUF);

        // ---- compute this half's 2 channels
#pragma unroll
        for (int cc = 0; cc < 2; cc++) {
            const int c = h * 2 + cc;
            float4 xv = *(const float4*)&S->xs[sel][c][row][j0];
            unsigned long long xlo, xhi;
            PACK2(xlo, xv.x, xv.y);
            PACK2(xhi, xv.z, xv.w);
#pragma unroll
            for (int a = 0; a < DI_CHUNK; a++) {
                float4 t0 = *(const float4*)&S->ys[sel][c][row + a][j0 + 0];
                float4 t1 = *(const float4*)&S->ys[sel][c][row + a][j0 + 4];
                float4 t2 = *(const float4*)&S->ys[sel][c][row + a][j0 + 8];
                float wv[12] = { t0.x, t0.y, t0.z, t0.w,
                                 t1.x, t1.y, t1.z, t1.w,
                                 t2.x, t2.y, t2.z, t2.w };
                unsigned long long wp[11];
#pragma unroll
                for (int k = 0; k < 11; k++) PACK2(wp[k], wv[k], wv[k + 1]);
#pragma unroll
                for (int d = 0; d < 9; d++) {
                    FMA2(acc2[a][d][0], xlo, wp[d]);
                    FMA2(acc2[a][d][1], xhi, wp[d + 2]);
                }
            }
        }
        __syncthreads();   // protect ring buffer reuse by next iteration's issue
    }

    // ---- cross-half reduction + store
    // half1 spills its 108 partials to smem; half0 adds, scales, stores.
    const int p = row * 16 + jg;   // 0..63, same for partner threads
    if (h == 1) {
#pragma unroll
        for (int a = 0; a < DI_CHUNK; a++)
#pragma unroll
            for (int d = 0; d < 9; d++) {
                float v0, v1, v2, v3;
                UNPK2(v0, v1, acc2[a][d][0]);
                UNPK2(v2, v3, acc2[a][d][1]);
                int k = (a * 9 + d) * 4;
                red[p][k + 0] = v0; red[p][k + 1] = v1;
                red[p][k + 2] = v2; red[p][k + 3] = v3;
            }
    }
    __syncthreads();
    if (h == 0) {
        const float s = 1.0f / (float)CH;
#pragma unroll
        for (int a = 0; a < DI_CHUNK; a++)
#pragma unroll
            for (int d = 0; d < 9; d++) {
                float v0, v1, v2, v3;
                UNPK2(v0, v1, acc2[a][d][0]);
                UNPK2(v2, v3, acc2[a][d][1]);
                int k = (a * 9 + d) * 4;
                float4 v = make_float4((v0 + red[p][k + 0]) * s,
                                       (v1 + red[p][k + 1]) * s,
                                       (v2 + red[p][k + 2]) * s,
                                       (v3 + red[p][k + 3]) * s);
                int dd = (g + a) * 9 + d;
                *(float4*)&out[(((size_t)b * 81 + dd) * HH + (i0 + row)) * WW + j0] = v;
            }
    }
}

extern "C" void kernel_launch(void* const* d_in, const int* in_sizes, int n_in,
                              void* d_out, int out_size)
{
    const float* x = (const float*)d_in[0];
    const float* y = (const float*)d_in[1];
    float* out = (float*)d_out;

    dim3 grid(HH / TH, 9 / DI_CHUNK, BB);   // (16, 3, 16) = 768 CTAs
    dim3 block(128);
    corr_kernel<<<grid, block>>>(x, y, out);
}

// round 13
// speedup vs baseline: 1.1060x; 1.1060x over previous
#include <cuda_runtime.h>
#include <cstdint>

// Spatial correlation sampler:
// out[b, di*9+dj, i, j] = (1/C) * sum_c x[b,c,i,j] * y[b,c,i+di-4, j+dj-4]  (zero-padded)
// x,y = [16, 256, 64, 64] fp32; out = [16, 81, 64, 64] fp32.

#define BB 16
#define CH 256
#define HH 64
#define WW 64
#define TH 8            // output rows per CTA
#define CC 4            // channels per smem stage
#define NS (CH / CC)    // 64 stages
#define DI_CHUNK 3
#define YR (TH + 2)     // 10 y rows per stage
#define YW 72           // 64 + 2*4 pad
#define XF4 (CC * TH * WW / 4)   // 512 float4 per x stage
#define YF4 (CC * YR * 18)       // 720 float4 per y stage
#define CHSTR (HH * WW)          // channel stride (floats)
#define STAGESTR (CC * CHSTR)    // gmem advance per stage (floats)

#define FMA2(acc, a, b) \
    asm("fma.rn.f32x2 %0, %1, %2, %0;" : "+l"(acc) : "l"(a), "l"(b))
#define PACK2(r, lo, hi) \
    asm("mov.b64 %0, {%1, %2};" : "=l"(r) : "r"(__float_as_uint(lo)), "r"(__float_as_uint(hi)))
#define UNPK2(lo, hi, r) \
    asm("mov.b64 {%0, %1}, %2;" : "=f"(lo), "=f"(hi) : "l"(r))

__device__ __forceinline__ void cpa16(uint32_t saddr, const void* gptr, int src_bytes) {
    asm volatile("cp.async.cg.shared.global [%0], [%1], 16, %2;\n"
                 :: "r"(saddr), "l"(gptr), "r"(src_bytes));
}

__global__ __launch_bounds__(128, 3)
void corr_kernel(const float* __restrict__ x,
                 const float* __restrict__ y,
                 float* __restrict__ out)
{
    __shared__ float xs[2][CC][TH][WW];   // 2 * 8 KB
    __shared__ float ys[2][CC][YR][YW];   // 2 * 11.25 KB  => 38.5 KB total

    const int tid = threadIdx.x;       // 128 threads
    const int jg  = tid & 15;
    const int ti  = tid >> 4;
    const int j0  = jg * 4;            // 4 pixels per thread
    const int i0  = blockIdx.x * TH;
    const int g   = blockIdx.y * DI_CHUNK;
    const int b   = blockIdx.z;        // batch slowest -> L2 locality across passes

    const float* xb = x + (size_t)b * CH * CHSTR;
    const float* yb = y + (size_t)b * CH * CHSTR;

    const uint32_t xs_s  = (uint32_t)__cvta_generic_to_shared(&xs[0][0][0][0]);
    const uint32_t ys_s  = (uint32_t)__cvta_generic_to_shared(&ys[0][0][0][0]);
    const uint32_t xs_sz = sizeof(float) * CC * TH * WW;
    const uint32_t ys_sz = sizeof(float) * CC * YR * YW;

    // ---- precompute per-thread loader addresses (hoisted out of the stage loop)
    // x tile: 512 float4 per stage -> 4 per thread
    const float* gx[4];  uint32_t sx[4];
#pragma unroll
    for (int e = 0; e < 4; e++) {
        int f   = tid + e * 128;
        int c   = f >> 7;             // / (TH*WW/4 = 128)
        int rem = f & 127;
        int r   = rem >> 4;
        int q4  = rem & 15;
        gx[e] = xb + c * CHSTR + (i0 + r) * WW + q4 * 4;
        sx[e] = xs_s + (uint32_t)f * 16u;
    }
    // y tile: 720 float4 per stage -> up to 6 per thread, zero-padded edges
    const float* gyp[6]; uint32_t sy[6]; int ybytes[6]; bool yvalid[6];
#pragma unroll
    for (int e = 0; e < 6; e++) {
        int f = tid + e * 128;
        yvalid[e] = (f < YF4);
        int fc = yvalid[e] ? f : 0;
        int c   = fc / (YR * 18);
        int rem = fc % (YR * 18);
        int r   = rem / 18;
        int q   = rem % 18;
        int gy  = i0 + g - 4 + r;
        bool ok = (gy >= 0) && (gy < HH) && (q > 0) && (q < 17);
        int gyc = gy < 0 ? 0 : (gy > HH - 1 ? HH - 1 : gy);
        int gq  = ok ? (q * 4 - 4) : 0;
        gyp[e]    = yb + c * CHSTR + gyc * WW + gq;
        sy[e]     = ys_s + (uint32_t)(((c * YR + r) * YW) + q * 4) * 4u;
        ybytes[e] = ok ? 16 : 0;
    }

    // f32x2 accumulators
    unsigned long long acc2[DI_CHUNK][9][2];
#pragma unroll
    for (int a = 0; a < DI_CHUNK; a++)
#pragma unroll
        for (int d = 0; d < 9; d++) { acc2[a][d][0] = 0ull; acc2[a][d][1] = 0ull; }

    // ---- issue one stage's cp.asyncs (call strictly sequentially: advances ptrs)
    auto issue_stage = [&](int sel) {
        uint32_t xo = sel ? xs_sz : 0u;
        uint32_t yo = sel ? ys_sz : 0u;
#pragma unroll
        for (int e = 0; e < 4; e++) {
            cpa16(sx[e] + xo, gx[e], 16);
            gx[e] += STAGESTR;
        }
#pragma unroll
        for (int e = 0; e < 6; e++) {
            if (yvalid[e]) {
                cpa16(sy[e] + yo, gyp[e], ybytes[e]);
                gyp[e] += STAGESTR;
            }
        }
        asm volatile("cp.async.commit_group;\n");
    };

    issue_stage(0);

    for (int t = 0; t < NS; t++) {
        const int sel = t & 1;
        asm volatile("cp.async.wait_group 0;\n");
        __syncthreads();                       // single barrier per stage
        if (t + 1 < NS) issue_stage(sel ^ 1);  // overlaps with compute below

        // ---- compute on buffer `sel`
#pragma unroll
        for (int c = 0; c < CC; c++) {
            float4 xv = *(const float4*)&xs[sel][c][ti][j0];
            unsigned long long xlo, xhi;
            PACK2(xlo, xv.x, xv.y);
            PACK2(xhi, xv.z, xv.w);
#pragma unroll
            for (int a = 0; a < DI_CHUNK; a++) {
                float4 t0 = *(const float4*)&ys[sel][c][ti + a][j0 + 0];
                float4 t1 = *(const float4*)&ys[sel][c][ti + a][j0 + 4];
                float4 t2 = *(const float4*)&ys[sel][c][ti + a][j0 + 8];
                float wv[12] = { t0.x, t0.y, t0.z, t0.w,
                                 t1.x, t1.y, t1.z, t1.w,
                                 t2.x, t2.y, t2.z, t2.w };
                unsigned long long wp[11];
#pragma unroll
                for (int k = 0; k < 11; k++) PACK2(wp[k], wv[k], wv[k + 1]);
#pragma unroll
                for (int d = 0; d < 9; d++) {
                    FMA2(acc2[a][d][0], xlo, wp[d]);
                    FMA2(acc2[a][d][1], xhi, wp[d + 2]);
                }
            }
        }
        // no trailing barrier: next iteration's top barrier protects buffer reuse
    }

    // ---- epilogue: scale by 1/C, coalesced float4 stores
    const float s = 1.0f / (float)CH;
#pragma unroll
    for (int a = 0; a < DI_CHUNK; a++) {
#pragma unroll
        for (int d = 0; d < 9; d++) {
            int dd = (g + a) * 9 + d;
            float v0, v1, v2, v3;
            UNPK2(v0, v1, acc2[a][d][0]);
            UNPK2(v2, v3, acc2[a][d][1]);
            float4 v = make_float4(v0 * s, v1 * s, v2 * s, v3 * s);
            *(float4*)&out[(((size_t)b * 81 + dd) * HH + (i0 + ti)) * WW + j0] = v;
        }
    }
}

extern "C" void kernel_launch(void* const* d_in, const int* in_sizes, int n_in,
                              void* d_out, int out_size)
{
    const float* x = (const float*)d_in[0];
    const float* y = (const float*)d_in[1];
    float* out = (float*)d_out;

    dim3 grid(HH / TH, 9 / DI_CHUNK, BB);   // (8, 3, 16) = 384 CTAs, single wave @ 3 CTA/SM
    dim3 block(128);
    corr_kernel<<<grid, block>>>(x, y, out);
}